// round 10
// baseline (speedup 1.0000x reference)
#include <cuda_runtime.h>
#include <cuda_bf16.h>

// Problem constants (fixed by the reference's setup)
#define SIZE   129
#define BZ2    64
#define BZX    65
#define MARGIN 3
#define GZ     135          // SIZE + 2*MARGIN
#define GY     135
#define GX     68           // BZX + MARGIN
#define GYGX   (GY * GX)
#define NPTS   (SIZE * BZX) // 8385
#define NBATCH 256
#define NIN    8

// 8 lanes cooperate per output point: o = lane&7, q = o&3 (16B quarter of the
// 64B weight row), h = o>>2 (dx half of the corner pair). One weight-gather
// instruction covers a full dx-pair (contiguous rows ~95% of the time, since
// the voxel index map is raster-ordered with x fastest) for 4 points, so pair
// rows share L1 lines within the instruction. Bias is 1 corner per lane.
__global__ __launch_bounds__(256, 8) void trilinear_proj_kernel(
    const float* __restrict__ input,    // [256, 8]
    const float* __restrict__ weight,   // [W, 8, 2]
    const float* __restrict__ bias,     // [W, 2]
    const int*   __restrict__ gidx,     // [135, 135, 68]
    const float* __restrict__ rot,      // [256, 3, 3]
    float*       __restrict__ out)      // [256, NPTS, 2]
{
    __shared__ float sIn[NIN];
    __shared__ float sR[9];

    const int b   = blockIdx.y;
    const int tid = threadIdx.x;
    if (tid < NIN) sIn[tid] = input[b * NIN + tid];
    if (tid < 9)   sR[tid]  = rot[b * 9 + tid];
    __syncthreads();

    const int t = blockIdx.x * 256 + tid;
    const int n = t >> 3;          // point index
    const int o = t & 7;           // lane within octet
    const int q = o & 3;           // 16B quarter
    const int h = o >> 2;          // dx half
    if (n >= NPTS) return;         // octet-granular -> octets stay intact

    // shfl mask covering exactly this octet
    const unsigned omask = 0xFFu << ((tid & 31) & ~7);

    // This lane's two input features
    const float iA = sIn[2 * q];
    const float iB = sIn[2 * q + 1];

    const float r00 = sR[0], r01 = sR[1];
    const float r10 = sR[3], r11 = sR[4];
    const float r20 = sR[6], r21 = sR[7];

    // grid2d coords derived arithmetically: n = iy*BZX + ix, y = iy-BZ2, x = ix
    const float y2 = (float)(n / BZX - BZ2);
    const float x2 = (float)(n % BZX);

    // c = R @ (x2, y2, 0), fp32, no fma contraction (bit-critical at the
    // r^2 = 4096 boundary lattice points, where one product is exactly zero).
    float cx = __fadd_rn(__fmul_rn(r00, x2), __fmul_rn(r01, y2));
    float cy = __fadd_rn(__fmul_rn(r10, x2), __fmul_rn(r11, y2));
    float cz = __fadd_rn(__fmul_rn(r20, x2), __fmul_rn(r21, y2));

    float sign = 1.0f;
    if (cx < 0.0f) { cx = -cx; cy = -cy; cz = -cz; sign = -1.0f; }

    // inside = sum(c*c) < 64^2 with the reference's Triton half-split tree:
    // q = (s1 + s3) + s2, rounded elementwise squares, no fma contraction.
    const float s1 = __fmul_rn(cx, cx);
    const float s2 = __fmul_rn(cy, cy);
    const float s3 = __fmul_rn(cz, cz);
    const float r2 = __fadd_rn(__fadd_rn(s1, s3), s2);
    const bool inside = (r2 < 4096.0f);

    float accR = 0.0f, accI = 0.0f;

    if (inside) {
        const float fxf = floorf(cx), fyf = floorf(cy), fzf = floorf(cz);
        const float fx = cx - fxf, fy = cy - fyf, fz = cz - fzf;

        // For inside points the reference's jnp.clip never binds
        // (bx in [0,63], by,bz in [-64,63]). Base + constant offsets + h.
        const int base = ((int)fzf + BZ2 + MARGIN) * GYGX
                       + ((int)fyf + BZ2 + MARGIN) * GX
                       + (int)fxf + h;

        // Each lane loads the 4 corners of its own dx-half (p = (dz,dy) pair)
        int ids[4];
        ids[0] = gidx[base];
        ids[1] = gidx[base + GX];
        ids[2] = gidx[base + GYGX];
        ids[3] = gidx[base + GYGX + GX];

        // Trilinear pair weights: wzy[p] * wx(h)
        const float wx  = h ? fx : (1.0f - fx);
        const float wy0 = 1.0f - fy, wy1 = fy;
        const float wz0 = 1.0f - fz, wz1 = fz;
        float wzy[4];
        wzy[0] = wz0 * wy0;
        wzy[1] = wz0 * wy1;
        wzy[2] = wz1 * wy0;
        wzy[3] = wz1 * wy1;

        const float* wbase = weight + q * 4;

        // Branch-free pair loop: one float4 quarter-row load per (pair,half)
        #pragma unroll
        for (int p = 0; p < 4; p++) {
            const int id   = ids[p];
            const int safe = max(id, 0);
            const float4 wq = *reinterpret_cast<const float4*>(
                wbase + (size_t)safe * 16);
            const float w = (id >= 0) ? (wzy[p] * wx) : 0.0f;
            accR += w * (iA * wq.x + iB * wq.z);
            accI += w * (iA * wq.y + iB * wq.w);
        }

        // Bias: lane (q,h) owns corner (p=q, h) -> all 8 corners covered once
        {
            const int idb  = ids[q];
            const int safe = max(idb, 0);
            const float2 bb = reinterpret_cast<const float2*>(bias)[safe];
            const float wb = (idb >= 0) ? (wzy[q] * wx) : 0.0f;
            accR += wb * bb.x;
            accI += wb * bb.y;
        }
    }

    // Combine the 8 partial sums of the octet
    accR += __shfl_xor_sync(omask, accR, 1);
    accI += __shfl_xor_sync(omask, accI, 1);
    accR += __shfl_xor_sync(omask, accR, 2);
    accI += __shfl_xor_sync(omask, accI, 2);
    accR += __shfl_xor_sync(omask, accR, 4);
    accI += __shfl_xor_sync(omask, accI, 4);

    if (o == 0) {
        float2* outp = reinterpret_cast<float2*>(out) + (size_t)b * NPTS + n;
        *outp = make_float2(accR, sign * accI);
    }
}

extern "C" void kernel_launch(void* const* d_in, const int* in_sizes, int n_in,
                              void* d_out, int out_size) {
    const float* input  = (const float*)d_in[0];
    const float* weight = (const float*)d_in[1];
    const float* bias   = (const float*)d_in[2];
    const int*   gidx   = (const int*)  d_in[3];
    const float* rot    = (const float*)d_in[4];
    // d_in[5] = grid2d_coord (derived arithmetically), d_in[6] = max_r (hardcoded)

    float* out = (float*)d_out;

    dim3 block(256);
    dim3 grid((NPTS * 8 + 255) / 256, NBATCH);   // 8 lanes per point
    trilinear_proj_kernel<<<grid, block>>>(input, weight, bias, gidx, rot, out);
}

// round 11
// speedup vs baseline: 1.1265x; 1.1265x over previous
#include <cuda_runtime.h>
#include <cuda_bf16.h>

// Problem constants (fixed by the reference's setup)
#define SIZE   129
#define BZ2    64
#define BZX    65
#define MARGIN 3
#define GZ     135          // SIZE + 2*MARGIN
#define GY     135
#define GX     68           // BZX + MARGIN
#define GYGX   (GY * GX)
#define NPTS   (SIZE * BZX) // 8385
#define NBATCH 256
#define NIN    8

// Hybrid layout: warp = 8 points.
//  - Prologue: lane l computes point nbase+(l>>2) (R9 layout: 4 lanes/point,
//    SIMD -> prologue issues ONCE per warp for 8 points).
//  - Gather: two phases; in phase s lane serves point s*4+(l>>3) with octet
//    role (q = 16B quarter of the weight row, h = dx half). One weight LDG
//    covers full dx-pairs (contiguous 128B ~95% of the time) for 4 points ->
//    fewer L1 lines per instruction than the 4-lane layout (R10's gather
//    economy) without R10's per-point prologue cost. Params bridged by shfl.
__global__ __launch_bounds__(256, 6) void trilinear_proj_kernel(
    const float* __restrict__ input,    // [256, 8]
    const float* __restrict__ weight,   // [W, 8, 2]
    const float* __restrict__ bias,     // [W, 2]
    const int*   __restrict__ gidx,     // [135, 135, 68]
    const float* __restrict__ rot,      // [256, 3, 3]
    float*       __restrict__ out)      // [256, NPTS, 2]
{
    __shared__ float sIn[NIN];
    __shared__ float sR[9];

    const int b   = blockIdx.y;
    const int tid = threadIdx.x;
    if (tid < NIN) sIn[tid] = input[b * NIN + tid];
    if (tid < 9)   sR[tid]  = rot[b * 9 + tid];
    __syncthreads();

    const int lane  = tid & 31;
    const int nbase = (blockIdx.x * 8 + (tid >> 5)) * 8;   // 8 points per warp
    const int n     = nbase + (lane >> 2);   // my prologue point
    const int q     = lane & 3;              // 16B quarter (same role in gather)

    const float iA = sIn[2 * q];
    const float iB = sIn[2 * q + 1];

    // ---- Prologue (R9 numerics, bit-exact w.r.t. the reference) ----
    const float y2 = (float)(n / BZX - BZ2);
    const float x2 = (float)(n % BZX);

    float cx = __fadd_rn(__fmul_rn(sR[0], x2), __fmul_rn(sR[1], y2));
    float cy = __fadd_rn(__fmul_rn(sR[3], x2), __fmul_rn(sR[4], y2));
    float cz = __fadd_rn(__fmul_rn(sR[6], x2), __fmul_rn(sR[7], y2));

    float sign = 1.0f;
    if (cx < 0.0f) { cx = -cx; cy = -cy; cz = -cz; sign = -1.0f; }

    // inside = sum(c*c) < 64^2, Triton half-split tree: (s1+s3)+s2, rounded
    // elementwise squares, no fma contraction (decision-critical expression).
    const float s1 = __fmul_rn(cx, cx);
    const float s2 = __fmul_rn(cy, cy);
    const float s3 = __fmul_rn(cz, cz);
    const float r2 = __fadd_rn(__fadd_rn(s1, s3), s2);
    const bool valid = (r2 < 4096.0f) && (n < NPTS);

    const float fxf = floorf(cx), fyf = floorf(cy), fzf = floorf(cz);
    const float fx = cx - fxf, fy = cy - fyf, fz = cz - fzf;

    // For inside points the reference's jnp.clip never binds
    // (bx in [0,63], by,bz in [-64,63]). Encode invalid as -1.
    int base = ((int)fzf + BZ2 + MARGIN) * GYGX
             + ((int)fyf + BZ2 + MARGIN) * GX
             + (int)fxf;
    base = valid ? base : -1;

    const int o = lane & 7;
    const int h = o >> 2;                 // dx half
    const float* wbase = weight + q * 4;

    // ---- Two gather phases: points s*4 .. s*4+3 ----
    #pragma unroll
    for (int s = 0; s < 2; s++) {
        const int p   = s * 4 + (lane >> 3);   // point served this phase
        const int src = p << 2;                // lane holding p's params

        const int   gb  = __shfl_sync(0xffffffffu, base, src);
        const float gfx = __shfl_sync(0xffffffffu, fx,   src);
        const float gfy = __shfl_sync(0xffffffffu, fy,   src);
        const float gfz = __shfl_sync(0xffffffffu, fz,   src);
        const float gsg = __shfl_sync(0xffffffffu, sign, src);

        float aR = 0.0f, aI = 0.0f;

        if (__ballot_sync(0xffffffffu, gb >= 0)) {   // warp-uniform skip
            const int bb = max(gb, 0) + h;

            // 4 corner-ids of my dx-half (invalid points read margin -1s)
            int ids[4];
            ids[0] = gidx[bb];
            ids[1] = gidx[bb + GX];
            ids[2] = gidx[bb + GYGX];
            ids[3] = gidx[bb + GYGX + GX];

            const float wxr = h ? gfx : (1.0f - gfx);
            const float wx  = (gb >= 0) ? wxr : 0.0f;  // fold point validity
            const float wy0 = 1.0f - gfy, wy1 = gfy;
            const float wz0 = 1.0f - gfz, wz1 = gfz;
            float wzy[4];
            wzy[0] = wz0 * wy0;
            wzy[1] = wz0 * wy1;
            wzy[2] = wz1 * wy0;
            wzy[3] = wz1 * wy1;

            #pragma unroll
            for (int k = 0; k < 4; k++) {
                const int id = ids[k];
                const float4 wq = *reinterpret_cast<const float4*>(
                    wbase + (size_t)max(id, 0) * 16);
                const float w = (id >= 0) ? (wzy[k] * wx) : 0.0f;
                aR += w * (iA * wq.x + iB * wq.z);
                aI += w * (iA * wq.y + iB * wq.w);
            }

            // Bias: lane (q,h) owns corner (p=q, h) -> 8 corners covered once
            {
                const int idb = ids[q];
                const float2 bb2 =
                    reinterpret_cast<const float2*>(bias)[max(idb, 0)];
                const float wb = (idb >= 0) ? (wzy[q] * wx) : 0.0f;
                aR += wb * bb2.x;
                aI += wb * bb2.y;
            }
        }

        // Octet reduction (converged: the guarded block is warp-uniform)
        aR += __shfl_xor_sync(0xffffffffu, aR, 1);
        aI += __shfl_xor_sync(0xffffffffu, aI, 1);
        aR += __shfl_xor_sync(0xffffffffu, aR, 2);
        aI += __shfl_xor_sync(0xffffffffu, aI, 2);
        aR += __shfl_xor_sync(0xffffffffu, aR, 4);
        aI += __shfl_xor_sync(0xffffffffu, aI, 4);

        const int pn = nbase + p;
        if (o == 0 && pn < NPTS) {
            float2* op = reinterpret_cast<float2*>(out) + (size_t)b * NPTS + pn;
            *op = make_float2(aR, gsg * aI);
        }
    }
}

extern "C" void kernel_launch(void* const* d_in, const int* in_sizes, int n_in,
                              void* d_out, int out_size) {
    const float* input  = (const float*)d_in[0];
    const float* weight = (const float*)d_in[1];
    const float* bias   = (const float*)d_in[2];
    const int*   gidx   = (const int*)  d_in[3];
    const float* rot    = (const float*)d_in[4];
    // d_in[5] = grid2d_coord (derived arithmetically), d_in[6] = max_r (hardcoded)

    float* out = (float*)d_out;

    dim3 block(256);
    dim3 grid((NPTS + 63) / 64, NBATCH);   // 8 warps/block, 8 points/warp
    trilinear_proj_kernel<<<grid, block>>>(input, weight, bias, gidx, rot, out);
}

// round 12
// speedup vs baseline: 1.1519x; 1.0226x over previous
#include <cuda_runtime.h>
#include <cuda_bf16.h>

// Problem constants (fixed by the reference's setup)
#define SIZE   129
#define BZ2    64
#define BZX    65
#define MARGIN 3
#define GZ     135          // SIZE + 2*MARGIN
#define GY     135
#define GX     68           // BZX + MARGIN
#define GYGX   (GY * GX)
#define NCELLS (GZ * GY * GX)   // 1,239,300
#define NPTS   (SIZE * BZX)     // 8385
#define NBATCH 256
#define NIN    8

// Pre-gathered per-cell tables (static zero-init; margin/invalid cells are
// never written and stay zero -> reproduces the reference's valid-masking).
// cellW: 16 floats per cell (the 8x2 weight row), cellB: 2 floats per cell.
__device__ float4 g_cellW[(size_t)NCELLS * 4];   // ~79 MB
__device__ float2 g_cellB[NCELLS];               // ~10 MB

// Stage 1: materialize cell tables. Reads are raster-ordered (consecutive
// valid cells have consecutive ids) -> effectively sequential; writes
// coalesced. Idempotent and deterministic (same inputs -> same tables).
__global__ __launch_bounds__(256) void build_tables_kernel(
    const float* __restrict__ weight,
    const float* __restrict__ bias,
    const int*   __restrict__ gidx)
{
    const int c = blockIdx.x * 256 + threadIdx.x;
    if (c >= NCELLS) return;
    const int gi = gidx[c];
    if (gi >= 0) {
        const float4* src = reinterpret_cast<const float4*>(weight + (size_t)gi * 16);
        float4* dst = g_cellW + (size_t)c * 4;
        dst[0] = src[0];
        dst[1] = src[1];
        dst[2] = src[2];
        dst[3] = src[3];
        g_cellB[c] = reinterpret_cast<const float2*>(bias)[gi];
    }
}

// Stage 2: projection. 4 lanes per point (lane q = 16B quarter of the 64B
// row). No index indirection, no validity masks: zeros in the tables carry
// the masking. Corner addresses of adjacent points are adjacent cells ->
// strong line sharing inside each gather instruction.
__global__ __launch_bounds__(256, 8) void trilinear_proj_kernel(
    const float* __restrict__ input,    // [256, 8]
    const float* __restrict__ rot,      // [256, 3, 3]
    float*       __restrict__ out)      // [256, NPTS, 2]
{
    __shared__ float sIn[NIN];
    __shared__ float sR[9];

    const int b   = blockIdx.y;
    const int tid = threadIdx.x;
    if (tid < NIN) sIn[tid] = input[b * NIN + tid];
    if (tid < 9)   sR[tid]  = rot[b * 9 + tid];
    __syncthreads();

    const int t = blockIdx.x * 256 + tid;
    const int n = t >> 2;          // point index
    const int q = t & 3;           // quarter within the weight row
    if (n >= NPTS) return;         // quad-granular -> quads stay intact

    const unsigned qmask = 0xFu << ((tid & 31) & ~3);

    const float iA = sIn[2 * q];
    const float iB = sIn[2 * q + 1];

    const float r00 = sR[0], r01 = sR[1];
    const float r10 = sR[3], r11 = sR[4];
    const float r20 = sR[6], r21 = sR[7];

    // grid2d coords derived arithmetically: n = iy*BZX + ix, y = iy-BZ2, x = ix
    const float y2 = (float)(n / BZX - BZ2);
    const float x2 = (float)(n % BZX);

    // c = R @ (x2, y2, 0), fp32, no fma contraction (bit-critical at the
    // r^2 = 4096 boundary lattice points, where one product is exactly zero).
    float cx = __fadd_rn(__fmul_rn(r00, x2), __fmul_rn(r01, y2));
    float cy = __fadd_rn(__fmul_rn(r10, x2), __fmul_rn(r11, y2));
    float cz = __fadd_rn(__fmul_rn(r20, x2), __fmul_rn(r21, y2));

    float sign = 1.0f;
    if (cx < 0.0f) { cx = -cx; cy = -cy; cz = -cz; sign = -1.0f; }

    // inside = sum(c*c) < 64^2 with the reference's Triton half-split tree:
    // q = (s1 + s3) + s2, rounded elementwise squares, no fma contraction.
    const float s1 = __fmul_rn(cx, cx);
    const float s2 = __fmul_rn(cy, cy);
    const float s3 = __fmul_rn(cz, cz);
    const float r2 = __fadd_rn(__fadd_rn(s1, s3), s2);
    const bool inside = (r2 < 4096.0f);

    float accR = 0.0f, accI = 0.0f;

    if (inside) {
        const float fxf = floorf(cx), fyf = floorf(cy), fzf = floorf(cz);
        const float fx = cx - fxf, fy = cy - fyf, fz = cz - fzf;

        // For inside points the reference's jnp.clip never binds
        // (bx in [0,63], by,bz in [-64,63]). Single base + constant offsets.
        const int base = ((int)fzf + BZ2 + MARGIN) * GYGX
                       + ((int)fyf + BZ2 + MARGIN) * GX
                       + (int)fxf;

        const float wx0 = 1.0f - fx, wx1 = fx;
        const float wy0 = 1.0f - fy, wy1 = fy;
        const float wz0 = 1.0f - fz, wz1 = fz;
        float cw[8];
        cw[0] = wz0 * wy0 * wx0;
        cw[1] = wz0 * wy0 * wx1;
        cw[2] = wz0 * wy1 * wx0;
        cw[3] = wz0 * wy1 * wx1;
        cw[4] = wz1 * wy0 * wx0;
        cw[5] = wz1 * wy0 * wx1;
        cw[6] = wz1 * wy1 * wx0;
        cw[7] = wz1 * wy1 * wx1;

        const int off[8] = {0, 1, GX, GX + 1,
                            GYGX, GYGX + 1, GYGX + GX, GYGX + GX + 1};
        const bool lane0 = (q == 0);

        // Branch-free corner loop: direct cell-indexed loads, no indirection,
        // no masks (invalid cells hold zeros).
        #pragma unroll
        for (int k = 0; k < 8; k++) {
            const int cell = base + off[k];
            const float4 wq = g_cellW[(size_t)cell * 4 + q];
            float vr = iA * wq.x + iB * wq.z;
            float vi = iA * wq.y + iB * wq.w;
            if (lane0) {
                const float2 bb = g_cellB[cell];
                vr += bb.x;
                vi += bb.y;
            }
            accR += cw[k] * vr;
            accI += cw[k] * vi;
        }
    }

    // Combine the 4 partial dots of the quad
    accR += __shfl_xor_sync(qmask, accR, 1);
    accI += __shfl_xor_sync(qmask, accI, 1);
    accR += __shfl_xor_sync(qmask, accR, 2);
    accI += __shfl_xor_sync(qmask, accI, 2);

    if (q == 0) {
        float2* o = reinterpret_cast<float2*>(out) + (size_t)b * NPTS + n;
        *o = make_float2(accR, sign * accI);
    }
}

extern "C" void kernel_launch(void* const* d_in, const int* in_sizes, int n_in,
                              void* d_out, int out_size) {
    const float* input  = (const float*)d_in[0];
    const float* weight = (const float*)d_in[1];
    const float* bias   = (const float*)d_in[2];
    const int*   gidx   = (const int*)  d_in[3];
    const float* rot    = (const float*)d_in[4];
    // d_in[5] = grid2d_coord (derived arithmetically), d_in[6] = max_r (hardcoded)

    float* out = (float*)d_out;

    // Stage 1: build pre-gathered cell tables (same stream -> ordered)
    build_tables_kernel<<<(NCELLS + 255) / 256, 256>>>(weight, bias, gidx);

    // Stage 2: projection
    dim3 block(256);
    dim3 grid((NPTS * 4 + 255) / 256, NBATCH);   // 4 lanes per point
    trilinear_proj_kernel<<<grid, block>>>(input, rot, out);
}

// round 13
// speedup vs baseline: 1.2557x; 1.0901x over previous
#include <cuda_runtime.h>
#include <cuda_bf16.h>

// Problem constants (fixed by the reference's setup)
#define SIZE   129
#define BZ2    64
#define BZX    65
#define MARGIN 3
#define GZ     135          // SIZE + 2*MARGIN
#define GY     135
#define GX     68           // BZX + MARGIN
#define GYGX   (GY * GX)
#define NCELLS (GZ * GY * GX)   // 1,239,300
#define NPTS   (SIZE * BZX)     // 8385
#define NBATCH 256
#define NIN    8

// 2D point tiling: block covers 8y x 8x points, warp covers 2y x 4x.
#define TILES_X 9    // ceil(65 / 8)
#define TILES_Y 17   // ceil(129 / 8)

// Pre-gathered per-cell tables (static zero-init; margin/invalid cells are
// never written and stay zero -> reproduces the reference's valid-masking).
__device__ float4 g_cellW[(size_t)NCELLS * 4];   // ~79 MB
__device__ float2 g_cellB[NCELLS];               // ~10 MB

// Stage 1: materialize cell tables (HBM-bound, ~13 us; reads raster-ordered).
__global__ __launch_bounds__(256) void build_tables_kernel(
    const float* __restrict__ weight,
    const float* __restrict__ bias,
    const int*   __restrict__ gidx)
{
    const int c = blockIdx.x * 256 + threadIdx.x;
    if (c >= NCELLS) return;
    const int gi = gidx[c];
    if (gi >= 0) {
        const float4* src = reinterpret_cast<const float4*>(weight + (size_t)gi * 16);
        float4* dst = g_cellW + (size_t)c * 4;
        dst[0] = src[0];
        dst[1] = src[1];
        dst[2] = src[2];
        dst[3] = src[3];
        g_cellB[c] = reinterpret_cast<const float2*>(bias)[gi];
    }
}

// Stage 2: projection. 4 lanes per point (lane q = 16B quarter of the row).
// Warp covers a 2y x 4x point tile: R's columns are orthonormal, so at most
// one tile direction maps near cell-z -> corner rows inside each gather
// instruction share lines along the other direction. Bias is distributed:
// lane q owns corners (dz=0,1; dy=q>>1; dx=q&1) with arithmetic offsets.
__global__ __launch_bounds__(256, 8) void trilinear_proj_kernel(
    const float* __restrict__ input,    // [256, 8]
    const float* __restrict__ rot,      // [256, 3, 3]
    float*       __restrict__ out)      // [256, NPTS, 2]
{
    __shared__ float sIn[NIN];
    __shared__ float sR[9];

    const int b   = blockIdx.y;
    const int tid = threadIdx.x;
    if (tid < NIN) sIn[tid] = input[b * NIN + tid];
    if (tid < 9)   sR[tid]  = rot[b * 9 + tid];
    __syncthreads();

    // Tile decomposition: block tile 8y x 8x, warps arranged 4y x 2x,
    // within-warp quads arranged 2y x 4x.
    const int tile = blockIdx.x;
    const int tx   = tile % TILES_X;
    const int ty   = tile / TILES_X;
    const int w    = tid >> 5;           // warp 0..7
    const int lane = tid & 31;
    const int quad = lane >> 2;          // 0..7
    const int q    = lane & 3;           // 16B quarter

    const int ix = tx * 8 + (w & 1) * 4 + (quad & 3);
    const int iy = ty * 8 + (w >> 1) * 2 + (quad >> 2);
    const bool inrange = (ix < BZX) && (iy < SIZE);

    const unsigned qmask = 0xFu << (lane & ~3);

    const float iA = sIn[2 * q];
    const float iB = sIn[2 * q + 1];

    const float x2 = (float)ix;
    const float y2 = (float)(iy - BZ2);

    // c = R @ (x2, y2, 0), fp32, no fma contraction (bit-critical at the
    // r^2 = 4096 boundary lattice points, where one product is exactly zero).
    float cx = __fadd_rn(__fmul_rn(sR[0], x2), __fmul_rn(sR[1], y2));
    float cy = __fadd_rn(__fmul_rn(sR[3], x2), __fmul_rn(sR[4], y2));
    float cz = __fadd_rn(__fmul_rn(sR[6], x2), __fmul_rn(sR[7], y2));

    float sign = 1.0f;
    if (cx < 0.0f) { cx = -cx; cy = -cy; cz = -cz; sign = -1.0f; }

    // inside = sum(c*c) < 64^2 with the reference's Triton half-split tree:
    // q = (s1 + s3) + s2, rounded elementwise squares, no fma contraction.
    const float s1 = __fmul_rn(cx, cx);
    const float s2 = __fmul_rn(cy, cy);
    const float s3 = __fmul_rn(cz, cz);
    const float r2 = __fadd_rn(__fadd_rn(s1, s3), s2);
    const bool inside = inrange && (r2 < 4096.0f);

    float accR = 0.0f, accI = 0.0f;

    if (inside) {
        const float fxf = floorf(cx), fyf = floorf(cy), fzf = floorf(cz);
        const float fx = cx - fxf, fy = cy - fyf, fz = cz - fzf;

        // For inside points the reference's jnp.clip never binds
        // (bx in [0,63], by,bz in [-64,63]). Single base + constant offsets.
        const int base = ((int)fzf + BZ2 + MARGIN) * GYGX
                       + ((int)fyf + BZ2 + MARGIN) * GX
                       + (int)fxf;

        const float wx0 = 1.0f - fx, wx1 = fx;
        const float wy0 = 1.0f - fy, wy1 = fy;
        const float wz0 = 1.0f - fz, wz1 = fz;
        float cw[8];
        cw[0] = wz0 * wy0 * wx0;
        cw[1] = wz0 * wy0 * wx1;
        cw[2] = wz0 * wy1 * wx0;
        cw[3] = wz0 * wy1 * wx1;
        cw[4] = wz1 * wy0 * wx0;
        cw[5] = wz1 * wy0 * wx1;
        cw[6] = wz1 * wy1 * wx0;
        cw[7] = wz1 * wy1 * wx1;

        const int off[8] = {0, 1, GX, GX + 1,
                            GYGX, GYGX + 1, GYGX + GX, GYGX + GX + 1};

        // Branch-free corner loop: direct cell-indexed loads, no indirection,
        // no masks (invalid cells hold zeros).
        #pragma unroll
        for (int k = 0; k < 8; k++) {
            const float4 wq = g_cellW[(size_t)(base + off[k]) * 4 + q];
            accR += cw[k] * (iA * wq.x + iB * wq.z);
            accI += cw[k] * (iA * wq.y + iB * wq.w);
        }

        // Distributed bias: lane q owns corners (dz=0,1; dy=q>>1; dx=q&1).
        // Offsets/weights derived arithmetically from q (no SEL chains).
        {
            const float wxq = (q & 1) ? fx : (1.0f - fx);
            const float wyq = (q & 2) ? fy : (1.0f - fy);
            const float wq01 = wyq * wxq;
            const int offb = (q >> 1) * GX + (q & 1);
            const float2 b0 = g_cellB[base + offb];
            const float2 b1 = g_cellB[base + offb + GYGX];
            const float w0 = wz0 * wq01;
            const float w1 = wz1 * wq01;
            accR += w0 * b0.x + w1 * b1.x;
            accI += w0 * b0.y + w1 * b1.y;
        }
    }

    // Combine the 4 partial dots of the quad
    accR += __shfl_xor_sync(qmask, accR, 1);
    accI += __shfl_xor_sync(qmask, accI, 1);
    accR += __shfl_xor_sync(qmask, accR, 2);
    accI += __shfl_xor_sync(qmask, accI, 2);

    if (q == 0 && inrange) {
        float2* o = reinterpret_cast<float2*>(out)
                  + (size_t)b * NPTS + iy * BZX + ix;
        *o = make_float2(accR, sign * accI);
    }
}

extern "C" void kernel_launch(void* const* d_in, const int* in_sizes, int n_in,
                              void* d_out, int out_size) {
    const float* input  = (const float*)d_in[0];
    const float* weight = (const float*)d_in[1];
    const float* bias   = (const float*)d_in[2];
    const int*   gidx   = (const int*)  d_in[3];
    const float* rot    = (const float*)d_in[4];
    // d_in[5] = grid2d_coord (derived arithmetically), d_in[6] = max_r (hardcoded)

    float* out = (float*)d_out;

    // Stage 1: build pre-gathered cell tables (same stream -> ordered)
    build_tables_kernel<<<(NCELLS + 255) / 256, 256>>>(weight, bias, gidx);

    // Stage 2: projection over 8x8 point tiles
    dim3 block(256);
    dim3 grid(TILES_X * TILES_Y, NBATCH);
    trilinear_proj_kernel<<<grid, block>>>(input, rot, out);
}

// round 14
// speedup vs baseline: 1.2760x; 1.0162x over previous
#include <cuda_runtime.h>
#include <cuda_bf16.h>

// Problem constants (fixed by the reference's setup)
#define SIZE   129
#define BZ2    64
#define BZX    65
#define MARGIN 3
#define GZ     135          // SIZE + 2*MARGIN
#define GY     135
#define GX     68           // BZX + MARGIN
#define GYGX   (GY * GX)
#define NCELLS (GZ * GY * GX)   // 1,239,300
#define NPTS   (SIZE * BZX)     // 8385
#define NBATCH 256
#define NIN    8

// 2D point tiling: block covers 8y x 8x points, warp covers 2y x 4x.
#define TILES_X 9    // ceil(65 / 8)
#define TILES_Y 17   // ceil(129 / 8)

typedef unsigned long long u64;

// Packed f32x2 helpers (sm_103a; ptxas aliases the packs of adjacent regs)
__device__ __forceinline__ u64 pk2(float lo, float hi) {
    u64 r; asm("mov.b64 %0, {%1, %2};" : "=l"(r) : "f"(lo), "f"(hi)); return r;
}
__device__ __forceinline__ u64 fma2(u64 a, u64 b, u64 c) {
    u64 d; asm("fma.rn.f32x2 %0, %1, %2, %3;" : "=l"(d) : "l"(a), "l"(b), "l"(c)); return d;
}
__device__ __forceinline__ u64 mul2(u64 a, u64 b) {
    u64 d; asm("mul.rn.f32x2 %0, %1, %2;" : "=l"(d) : "l"(a), "l"(b)); return d;
}

// Pre-gathered per-cell tables (static zero-init; margin/invalid cells are
// never written and stay zero -> reproduces the reference's valid-masking).
__device__ float4 g_cellW[(size_t)NCELLS * 4];   // ~79 MB
__device__ float2 g_cellB[NCELLS];               // ~10 MB

// Stage 1: materialize cell tables (HBM-bound, ~13-15 us).
__global__ __launch_bounds__(256) void build_tables_kernel(
    const float* __restrict__ weight,
    const float* __restrict__ bias,
    const int*   __restrict__ gidx)
{
    const int c = blockIdx.x * 256 + threadIdx.x;
    if (c >= NCELLS) return;
    const int gi = gidx[c];
    if (gi >= 0) {
        const float4* src = reinterpret_cast<const float4*>(weight + (size_t)gi * 16);
        float4* dst = g_cellW + (size_t)c * 4;
        dst[0] = src[0];
        dst[1] = src[1];
        dst[2] = src[2];
        dst[3] = src[3];
        g_cellB[c] = reinterpret_cast<const float2*>(bias)[gi];
    }
}

// Stage 2: projection. 4 lanes per point (lane q = 16B quarter of the row),
// warp = 2y x 4x point tile, distributed arithmetic bias, packed f32x2
// accumulation, flat byte-pointer addressing with constant immediates.
__global__ __launch_bounds__(256, 7) void trilinear_proj_kernel(
    const float* __restrict__ input,    // [256, 8]
    const float* __restrict__ rot,      // [256, 3, 3]
    float*       __restrict__ out)      // [256, NPTS, 2]
{
    __shared__ float sIn[NIN];
    __shared__ float sR[9];

    const int b   = blockIdx.y;
    const int tid = threadIdx.x;
    if (tid < NIN) sIn[tid] = input[b * NIN + tid];
    if (tid < 9)   sR[tid]  = rot[b * 9 + tid];
    __syncthreads();

    // Tile decomposition: block tile 8y x 8x, warps arranged 4y x 2x,
    // within-warp quads arranged 2y x 4x.
    const int tile = blockIdx.x;
    const int tx   = tile % TILES_X;
    const int ty   = tile / TILES_X;
    const int w    = tid >> 5;           // warp 0..7
    const int lane = tid & 31;
    const int quad = lane >> 2;          // 0..7
    const int q    = lane & 3;           // 16B quarter

    const int ix = tx * 8 + (w & 1) * 4 + (quad & 3);
    const int iy = ty * 8 + (w >> 1) * 2 + (quad >> 2);
    const bool inrange = (ix < BZX) && (iy < SIZE);

    const unsigned qmask = 0xFu << (lane & ~3);

    const float iA = sIn[2 * q];
    const float iB = sIn[2 * q + 1];

    const float x2 = (float)ix;
    const float y2 = (float)(iy - BZ2);

    // c = R @ (x2, y2, 0), fp32, no fma contraction (bit-critical at the
    // r^2 = 4096 boundary lattice points, where one product is exactly zero).
    float cx = __fadd_rn(__fmul_rn(sR[0], x2), __fmul_rn(sR[1], y2));
    float cy = __fadd_rn(__fmul_rn(sR[3], x2), __fmul_rn(sR[4], y2));
    float cz = __fadd_rn(__fmul_rn(sR[6], x2), __fmul_rn(sR[7], y2));

    float sign = 1.0f;
    if (cx < 0.0f) { cx = -cx; cy = -cy; cz = -cz; sign = -1.0f; }

    // inside = sum(c*c) < 64^2 with the reference's Triton half-split tree:
    // q = (s1 + s3) + s2, rounded elementwise squares, no fma contraction.
    const float s1 = __fmul_rn(cx, cx);
    const float s2 = __fmul_rn(cy, cy);
    const float s3 = __fmul_rn(cz, cz);
    const float r2 = __fadd_rn(__fadd_rn(s1, s3), s2);
    const bool inside = inrange && (r2 < 4096.0f);

    float accR = 0.0f, accI = 0.0f;

    if (inside) {
        const float fxf = floorf(cx), fyf = floorf(cy), fzf = floorf(cz);
        const float fx = cx - fxf, fy = cy - fyf, fz = cz - fzf;

        // For inside points the reference's jnp.clip never binds
        // (bx in [0,63], by,bz in [-64,63]). Single base + constant offsets.
        const int base = ((int)fzf + BZ2 + MARGIN) * GYGX
                       + ((int)fyf + BZ2 + MARGIN) * GX
                       + (int)fxf;

        const float wx0 = 1.0f - fx, wx1 = fx;
        const float wy0 = 1.0f - fy, wy1 = fy;
        const float wz0 = 1.0f - fz, wz1 = fz;
        float cw[8];
        cw[0] = wz0 * wy0 * wx0;
        cw[1] = wz0 * wy0 * wx1;
        cw[2] = wz0 * wy1 * wx0;
        cw[3] = wz0 * wy1 * wx1;
        cw[4] = wz1 * wy0 * wx0;
        cw[5] = wz1 * wy0 * wx1;
        cw[6] = wz1 * wy1 * wx0;
        cw[7] = wz1 * wy1 * wx1;

        // Flat byte base: corner loads become base-ptr + constant immediate
        const char* wp = reinterpret_cast<const char*>(g_cellW)
                       + (size_t)base * 64 + q * 16;

        const u64 iA2 = pk2(iA, iA);
        const u64 iB2 = pk2(iB, iB);
        u64 acc = 0;   // (accR, accI) = (0.0f, 0.0f)

        #pragma unroll
        for (int k = 0; k < 8; k++) {
            const int koff = ((k & 1) ? 64 : 0)
                           + ((k & 2) ? GX * 64 : 0)
                           + ((k & 4) ? GYGX * 64 : 0);
            const float4 wq = *reinterpret_cast<const float4*>(wp + koff);
            u64 v = mul2(iA2, pk2(wq.x, wq.y));
            v     = fma2(iB2, pk2(wq.z, wq.w), v);
            acc   = fma2(pk2(cw[k], cw[k]), v, acc);
        }

        // Distributed bias: lane q owns corners (dz=0,1; dy=q>>1; dx=q&1).
        {
            const float wxq = (q & 1) ? fx : (1.0f - fx);
            const float wyq = (q & 2) ? fy : (1.0f - fy);
            const float wq01 = wyq * wxq;
            const char* bp = reinterpret_cast<const char*>(g_cellB)
                           + (size_t)(base + (q >> 1) * GX + (q & 1)) * 8;
            const float2 b0 = *reinterpret_cast<const float2*>(bp);
            const float2 b1 = *reinterpret_cast<const float2*>(bp + GYGX * 8);
            const float w0 = wz0 * wq01;
            const float w1 = wz1 * wq01;
            acc = fma2(pk2(w0, w0), pk2(b0.x, b0.y), acc);
            acc = fma2(pk2(w1, w1), pk2(b1.x, b1.y), acc);
        }

        asm("mov.b64 {%0, %1}, %2;" : "=f"(accR), "=f"(accI) : "l"(acc));
    }

    // Combine the 4 partial dots of the quad
    accR += __shfl_xor_sync(qmask, accR, 1);
    accI += __shfl_xor_sync(qmask, accI, 1);
    accR += __shfl_xor_sync(qmask, accR, 2);
    accI += __shfl_xor_sync(qmask, accI, 2);

    if (q == 0 && inrange) {
        float2* o = reinterpret_cast<float2*>(out)
                  + (size_t)b * NPTS + iy * BZX + ix;
        *o = make_float2(accR, sign * accI);
    }
}

extern "C" void kernel_launch(void* const* d_in, const int* in_sizes, int n_in,
                              void* d_out, int out_size) {
    const float* input  = (const float*)d_in[0];
    const float* weight = (const float*)d_in[1];
    const float* bias   = (const float*)d_in[2];
    const int*   gidx   = (const int*)  d_in[3];
    const float* rot    = (const float*)d_in[4];
    // d_in[5] = grid2d_coord (derived arithmetically), d_in[6] = max_r (hardcoded)

    float* out = (float*)d_out;

    // Stage 1: build pre-gathered cell tables (same stream -> ordered)
    build_tables_kernel<<<(NCELLS + 255) / 256, 256>>>(weight, bias, gidx);

    // Stage 2: projection over 8x8 point tiles
    dim3 block(256);
    dim3 grid(TILES_X * TILES_Y, NBATCH);
    trilinear_proj_kernel<<<grid, block>>>(input, rot, out);
}